// round 3
// baseline (speedup 1.0000x reference)
#include <cuda_runtime.h>

#define N_NODES 10000
#define NHID    128
#define NEDGE   320000
#define NTILES  157   // ceil(10000/64)

// ---- scratch (device globals; no allocation allowed) ----
__device__ float g_xw [N_NODES * NHID];  // x @ W
__device__ float g_agg[N_NODES * NHID];  // edge-aggregated messages
__device__ float g_h  [N_NODES * NHID];  // relu(gcn) output
__device__ float g_deg[N_NODES];
__device__ float g_dinv[N_NODES];
__device__ int   g_row[NEDGE];
__device__ int   g_col[NEDGE];
__device__ int   g_is32;                 // 1 if edge_index stored as int32

// ---- detect edge_index dtype: int64 values <10000 have zero high words ----
// Scans odd int32 positions within the first 640,000 words (safe both ways).
__global__ void k_detect(const int* __restrict__ ei32) {
    int i = blockIdx.x * blockDim.x + threadIdx.x;   // word pair index
    // check odd positions 1,3,...  over first 2*NEDGE words
    if (i < NEDGE) {
        if (ei32[2 * i + 1] != 0) atomicExch(&g_is32, 1);
    }
}

// ---- convert edge list to clean int32 row/col with guards ----
__global__ void k_convert(const void* __restrict__ ei_raw) {
    int e = blockIdx.x * blockDim.x + threadIdx.x;
    if (e >= NEDGE) return;
    int r, c;
    if (g_is32) {
        const int* p = (const int*)ei_raw;
        r = p[e]; c = p[NEDGE + e];
    } else {
        const long long* p = (const long long*)ei_raw;
        r = (int)p[e]; c = (int)p[NEDGE + e];
    }
    if (r < 0 || r >= N_NODES) r = 0;
    if (c < 0 || c >= N_NODES) c = 0;
    g_row[e] = r;
    g_col[e] = c;
}

// ---- zero accumulators + detection flag (graph replay: re-zero each launch) ----
__global__ void k_zero() {
    int stride = gridDim.x * blockDim.x;
    int i = blockIdx.x * blockDim.x + threadIdx.x;
    if (i == 0) g_is32 = 0;
    for (int t = i; t < N_NODES * NHID; t += stride) g_agg[t] = 0.0f;
    for (int t = i; t < N_NODES;        t += stride) g_deg[t] = 0.0f;
}

// ---- degree of incoming edges at target ----
__global__ void k_deg() {
    int e = blockIdx.x * blockDim.x + threadIdx.x;
    if (e < NEDGE) atomicAdd(&g_deg[g_col[e]], 1.0f);
}

// ---- dinv = rsqrt(deg + 1)  (+1 self loop; always > 0) ----
__global__ void k_dinv() {
    int i = blockIdx.x * blockDim.x + threadIdx.x;
    if (i < N_NODES) g_dinv[i] = rsqrtf(g_deg[i] + 1.0f);
}

// ---- xw[n, c] = sum_k x[n,k] * W[k,c] ; one block per node ----
__global__ void k_xw(const float* __restrict__ x, const float* __restrict__ W) {
    __shared__ float xs[NHID];
    int n = blockIdx.x;
    int t = threadIdx.x;
    xs[t] = x[n * NHID + t];
    __syncthreads();
    float acc = 0.0f;
#pragma unroll 8
    for (int k = 0; k < NHID; k++)
        acc = fmaf(xs[k], W[k * NHID + t], acc);
    g_xw[n * NHID + t] = acc;
}

// ---- edge scatter: agg[col] += dinv[row]*dinv[col] * xw[row]; warp per edge ----
__global__ void k_edge() {
    int gw     = (blockIdx.x * blockDim.x + threadIdx.x) >> 5;
    int lane   = threadIdx.x & 31;
    int nwarps = (gridDim.x * blockDim.x) >> 5;
    for (int e = gw; e < NEDGE; e += nwarps) {
        int r = g_row[e];
        int c = g_col[e];
        float nf = g_dinv[r] * g_dinv[c];
        float4 v = *(const float4*)(&g_xw[r * NHID + lane * 4]);
        float* dst = &g_agg[c * NHID + lane * 4];
        atomicAdd(dst + 0, nf * v.x);
        atomicAdd(dst + 1, nf * v.y);
        atomicAdd(dst + 2, nf * v.z);
        atomicAdd(dst + 3, nf * v.w);
    }
}

// ---- h = relu(agg + dinv^2 * xw + b)   (self-loop folded in here) ----
__global__ void k_relu(const float* __restrict__ b) {
    int idx = blockIdx.x * blockDim.x + threadIdx.x;
    if (idx < N_NODES * NHID) {
        int node = idx >> 7;
        int f    = idx & 127;
        float di = g_dinv[node];
        float v  = g_agg[idx] + di * di * g_xw[idx] + b[f];
        g_h[idx] = fmaxf(v, 0.0f);
    }
}

// ---- out = h @ h^T, symmetric: compute upper-tri 64x64 block tiles, mirror ----
__global__ void k_gemm(float* __restrict__ out) {
    int bi = blockIdx.y, bj = blockIdx.x;
    if (bj < bi) return;                    // upper triangle only

    __shared__ float As[16][68];            // [k][row], padded row-stride 68
    __shared__ float Bs[16][68];

    int t  = threadIdx.x;                   // 256 threads
    int tx = t & 15, ty = t >> 4;
    int lr = t >> 2;                        // 0..63  (load row)
    int lc = (t & 3) << 2;                  // 0,4,8,12 (load k-offset)

    int rowA = bi * 64 + lr;
    int rowB = bj * 64 + lr;
    const float* hA = g_h + (long)rowA * NHID;
    const float* hB = g_h + (long)rowB * NHID;

    float acc[4][4] = {};

    for (int kk = 0; kk < NHID; kk += 16) {
        float4 a4 = (rowA < N_NODES) ? *(const float4*)(hA + kk + lc)
                                     : make_float4(0.f, 0.f, 0.f, 0.f);
        float4 b4 = (rowB < N_NODES) ? *(const float4*)(hB + kk + lc)
                                     : make_float4(0.f, 0.f, 0.f, 0.f);
        __syncthreads();
        As[lc + 0][lr] = a4.x; As[lc + 1][lr] = a4.y;
        As[lc + 2][lr] = a4.z; As[lc + 3][lr] = a4.w;
        Bs[lc + 0][lr] = b4.x; Bs[lc + 1][lr] = b4.y;
        Bs[lc + 2][lr] = b4.z; Bs[lc + 3][lr] = b4.w;
        __syncthreads();
#pragma unroll
        for (int k = 0; k < 16; k++) {
            float4 av = *(const float4*)&As[k][ty * 4];
            float4 bv = *(const float4*)&Bs[k][tx * 4];
            float ra[4] = {av.x, av.y, av.z, av.w};
            float rb[4] = {bv.x, bv.y, bv.z, bv.w};
#pragma unroll
            for (int i = 0; i < 4; i++)
#pragma unroll
                for (int j = 0; j < 4; j++)
                    acc[i][j] = fmaf(ra[i], rb[j], acc[i][j]);
        }
    }

    int ri0 = bi * 64 + ty * 4;
    int cj0 = bj * 64 + tx * 4;
    bool interior = (bi != NTILES - 1) && (bj != NTILES - 1);

    if (interior) {
#pragma unroll
        for (int i = 0; i < 4; i++) {
            float4 v = make_float4(acc[i][0], acc[i][1], acc[i][2], acc[i][3]);
            *(float4*)&out[(long)(ri0 + i) * N_NODES + cj0] = v;
        }
        if (bi != bj) {
#pragma unroll
            for (int j = 0; j < 4; j++) {
                float4 v = make_float4(acc[0][j], acc[1][j], acc[2][j], acc[3][j]);
                *(float4*)&out[(long)(cj0 + j) * N_NODES + ri0] = v;
            }
        }
    } else {
#pragma unroll
        for (int i = 0; i < 4; i++)
#pragma unroll
            for (int j = 0; j < 4; j++) {
                int r = ri0 + i, c = cj0 + j;
                if (r < N_NODES && c < N_NODES) out[(long)r * N_NODES + c] = acc[i][j];
            }
        if (bi != bj) {
#pragma unroll
            for (int i = 0; i < 4; i++)
#pragma unroll
                for (int j = 0; j < 4; j++) {
                    int r = ri0 + i, c = cj0 + j;
                    if (r < N_NODES && c < N_NODES) out[(long)c * N_NODES + r] = acc[i][j];
                }
        }
    }
}

extern "C" void kernel_launch(void* const* d_in, const int* in_sizes, int n_in,
                              void* d_out, int out_size) {
    // Identify inputs by element count (order-proof):
    //   x: 1,280,000 | edge_index: 640,000 (int32 OR int64 — detected on device)
    //   W: 16,384    | b: 128
    const float* x  = nullptr;
    const void*  ei = nullptr;
    const float* W  = nullptr;
    const float* b  = nullptr;
    for (int i = 0; i < n_in; i++) {
        switch (in_sizes[i]) {
            case N_NODES * NHID: x  = (const float*)d_in[i]; break;
            case 2 * NEDGE:      ei = d_in[i];               break;
            case NHID * NHID:    W  = (const float*)d_in[i]; break;
            case NHID:           b  = (const float*)d_in[i]; break;
            default: break;
        }
    }
    float* out = (float*)d_out;

    k_zero   <<<1024, 256>>>();
    k_detect <<<(NEDGE + 255) / 256, 256>>>((const int*)ei);
    k_convert<<<(NEDGE + 255) / 256, 256>>>(ei);
    k_deg    <<<(NEDGE + 255) / 256, 256>>>();
    k_dinv   <<<(N_NODES + 255) / 256, 256>>>();
    k_xw     <<<N_NODES, NHID>>>(x, W);
    k_edge   <<<2048, 256>>>();
    k_relu   <<<(N_NODES * NHID + 255) / 256, 256>>>(b);
    dim3 g(NTILES, NTILES);
    k_gemm<<<g, 256>>>(out);
}

// round 4
// speedup vs baseline: 1.9685x; 1.9685x over previous
#include <cuda_runtime.h>
#include <cuda_bf16.h>

#define N_NODES 10000
#define NHID    128
#define NEDGE   320000
#define NT      79            // ceil(10000/128)
#define NPAD    (NT * 128)    // 10112

// ---- scratch (device globals; no allocation allowed) ----
__device__ float          g_xw  [N_NODES * NHID];   // x @ W (fp32)
__device__ __nv_bfloat16  g_hb  [NPAD   * NHID];    // relu(gcn) in bf16, zero-padded rows
__device__ float          g_dinv[N_NODES];
__device__ int            g_row [NEDGE];
__device__ int            g_col [NEDGE];
__device__ int            g_cnt [N_NODES];          // in-degree (histogram)
__device__ int            g_base[N_NODES];          // CSR segment base
__device__ int            g_cur [N_NODES];          // fill cursor
__device__ int            g_src [NEDGE];            // source node per CSR slot
__device__ int            g_is32;

// ---- zero counters + pad rows (graph replay: re-run every launch) ----
__global__ void k_zero() {
    int i = blockIdx.x * blockDim.x + threadIdx.x;
    int stride = gridDim.x * blockDim.x;
    if (i == 0) g_is32 = 0;
    for (int t = i; t < N_NODES; t += stride) { g_cnt[t] = 0; g_cur[t] = 0; }
    // zero tail rows of g_hb (N_NODES..NPAD)
    const int tail = (NPAD - N_NODES) * NHID;   // 14336
    for (int t = i; t < tail; t += stride) g_hb[N_NODES * NHID + t] = __float2bfloat16(0.0f);
}

// ---- detect edge_index dtype (int64 values <10000 have zero high words) ----
__global__ void k_detect(const int* __restrict__ ei32) {
    int i = blockIdx.x * blockDim.x + threadIdx.x;
    if (i < NEDGE) {
        if (ei32[2 * i + 1] != 0) atomicExch(&g_is32, 1);
    }
}

// ---- convert edge list to clean int32 row/col with guards ----
__global__ void k_convert(const void* __restrict__ ei_raw) {
    int e = blockIdx.x * blockDim.x + threadIdx.x;
    if (e >= NEDGE) return;
    int r, c;
    if (g_is32) {
        const int* p = (const int*)ei_raw;
        r = p[e]; c = p[NEDGE + e];
    } else {
        const long long* p = (const long long*)ei_raw;
        r = (int)p[e]; c = (int)p[NEDGE + e];
    }
    if (r < 0 || r >= N_NODES) r = 0;
    if (c < 0 || c >= N_NODES) c = 0;
    g_row[e] = r;
    g_col[e] = c;
}

// ---- histogram of incoming edges at target ----
__global__ void k_hist() {
    int e = blockIdx.x * blockDim.x + threadIdx.x;
    if (e < NEDGE) atomicAdd(&g_cnt[g_col[e]], 1);
}

// ---- exclusive prefix sum over g_cnt -> g_base (single block) ----
__global__ void k_scan() {
    __shared__ int sums[256];
    const int CH = 40;                      // 256*40 = 10240 >= N_NODES
    int t = threadIdx.x;
    int s = 0;
    for (int j = 0; j < CH; j++) {
        int n = t * CH + j;
        if (n < N_NODES) s += g_cnt[n];
    }
    sums[t] = s;
    __syncthreads();
    for (int off = 1; off < 256; off <<= 1) {
        int v = (t >= off) ? sums[t - off] : 0;
        __syncthreads();
        sums[t] += v;
        __syncthreads();
    }
    int run = (t > 0) ? sums[t - 1] : 0;
    for (int j = 0; j < CH; j++) {
        int n = t * CH + j;
        if (n < N_NODES) { g_base[n] = run; run += g_cnt[n]; }
    }
}

// ---- dinv = rsqrt(deg + 1)  (+1 self loop; always > 0) ----
__global__ void k_dinv() {
    int i = blockIdx.x * blockDim.x + threadIdx.x;
    if (i < N_NODES) g_dinv[i] = rsqrtf((float)g_cnt[i] + 1.0f);
}

// ---- fill CSR: group source nodes by target ----
__global__ void k_fill() {
    int e = blockIdx.x * blockDim.x + threadIdx.x;
    if (e < NEDGE) {
        int c = g_col[e];
        int pos = g_base[c] + atomicAdd(&g_cur[c], 1);
        g_src[pos] = g_row[e];
    }
}

// ---- xw[n, c] = sum_k x[n,k] * W[k,c] ; one block per node ----
__global__ void k_xw(const float* __restrict__ x, const float* __restrict__ W) {
    __shared__ float xs[NHID];
    int n = blockIdx.x;
    int t = threadIdx.x;
    xs[t] = x[n * NHID + t];
    __syncthreads();
    float acc = 0.0f;
#pragma unroll 8
    for (int k = 0; k < NHID; k++)
        acc = fmaf(xs[k], W[k * NHID + t], acc);
    g_xw[n * NHID + t] = acc;
}

// ---- SpMM gather + self-loop + bias + relu + bf16 convert, fused ----
// one block (128 threads) per target node; no atomics.
__global__ void k_spmm(const float* __restrict__ b) {
    int c = blockIdx.x;
    int t = threadIdx.x;
    int base = g_base[c];
    int cnt  = g_cnt[c];
    float acc = 0.0f;
    int r = (cnt > 0) ? g_src[base] : 0;
    for (int i = 0; i < cnt; i++) {
        int rn = (i + 1 < cnt) ? g_src[base + i + 1] : 0;   // prefetch next src
        acc = fmaf(g_dinv[r], g_xw[r * NHID + t], acc);
        r = rn;
    }
    float dc = g_dinv[c];
    float v  = dc * acc + dc * dc * g_xw[c * NHID + t] + b[t];
    g_hb[c * NHID + t] = __float2bfloat16(fmaxf(v, 0.0f));
}

// ---- out = h @ h^T via bf16 mma.sync, symmetric 128x128 tiles ----
__global__ void __launch_bounds__(256) k_gemm(float* __restrict__ out) {
    int bi = blockIdx.y, bj = blockIdx.x;
    if (bj < bi) return;

    __shared__ __align__(16) __nv_bfloat16 As[128][72];   // 64 k-cols + 8 pad
    __shared__ __align__(16) __nv_bfloat16 Bs[128][72];

    int t    = threadIdx.x;        // 256
    int lane = t & 31;
    int wid  = t >> 5;             // 8 warps: 4 (m) x 2 (n)
    int wm   = wid & 3;            // warp m: 32 rows
    int wn   = wid >> 2;           // warp n: 64 cols
    int g    = lane >> 2;          // groupID 0..7
    int tq   = lane & 3;           // thread-in-group

    float acc[2][8][4] = {};       // [m-tile][n-tile][c0..c3]

    int lrow = t >> 3;             // 0..31 (load row per pass)
    int lk   = (t & 7) * 8;        // bf16 col offset, 16B chunks

    for (int kk0 = 0; kk0 < NHID; kk0 += 64) {
        // load 128x64 bf16 tiles (4 passes of 32 rows)
        __syncthreads();
#pragma unroll
        for (int p = 0; p < 4; p++) {
            int row = p * 32 + lrow;
            uint4 va = *(const uint4*)&g_hb[((long)(bi * 128 + row)) * NHID + kk0 + lk];
            uint4 vb = *(const uint4*)&g_hb[((long)(bj * 128 + row)) * NHID + kk0 + lk];
            *(uint4*)&As[row][lk] = va;
            *(uint4*)&Bs[row][lk] = vb;
        }
        __syncthreads();

#pragma unroll
        for (int ks = 0; ks < 4; ks++) {
            int k0 = ks * 16;
            unsigned a[2][4], bfr[8][2];
#pragma unroll
            for (int mi = 0; mi < 2; mi++) {
                int am = wm * 32 + mi * 16;
                a[mi][0] = *(const unsigned*)&As[am + g    ][k0 + 2 * tq    ];
                a[mi][1] = *(const unsigned*)&As[am + g + 8][k0 + 2 * tq    ];
                a[mi][2] = *(const unsigned*)&As[am + g    ][k0 + 2 * tq + 8];
                a[mi][3] = *(const unsigned*)&As[am + g + 8][k0 + 2 * tq + 8];
            }
#pragma unroll
            for (int ni = 0; ni < 8; ni++) {
                int bn = wn * 64 + ni * 8;
                bfr[ni][0] = *(const unsigned*)&Bs[bn + g][k0 + 2 * tq    ];
                bfr[ni][1] = *(const unsigned*)&Bs[bn + g][k0 + 2 * tq + 8];
            }
#pragma unroll
            for (int mi = 0; mi < 2; mi++)
#pragma unroll
                for (int ni = 0; ni < 8; ni++) {
                    float* d = acc[mi][ni];
                    asm volatile(
                        "mma.sync.aligned.m16n8k16.row.col.f32.bf16.bf16.f32 "
                        "{%0,%1,%2,%3}, {%4,%5,%6,%7}, {%8,%9}, {%0,%1,%2,%3};"
                        : "+f"(d[0]), "+f"(d[1]), "+f"(d[2]), "+f"(d[3])
                        : "r"(a[mi][0]), "r"(a[mi][1]), "r"(a[mi][2]), "r"(a[mi][3]),
                          "r"(bfr[ni][0]), "r"(bfr[ni][1]));
                }
        }
    }

    // epilogue
    bool interior = (bi != NT - 1) && (bj != NT - 1);
    int rbase = bi * 128 + wm * 32;
    int cbase = bj * 128 + wn * 64;
#pragma unroll
    for (int mi = 0; mi < 2; mi++) {
#pragma unroll
        for (int ni = 0; ni < 8; ni++) {
            int r0 = rbase + mi * 16 + g;
            int c0 = cbase + ni * 8 + 2 * tq;
            float* d = acc[mi][ni];
            if (interior) {
                *(float2*)&out[(long)r0 * N_NODES + c0]       = make_float2(d[0], d[1]);
                *(float2*)&out[(long)(r0 + 8) * N_NODES + c0] = make_float2(d[2], d[3]);
                if (bi != bj) {
                    out[(long)c0 * N_NODES + r0]           = d[0];
                    out[(long)(c0 + 1) * N_NODES + r0]     = d[1];
                    out[(long)c0 * N_NODES + r0 + 8]       = d[2];
                    out[(long)(c0 + 1) * N_NODES + r0 + 8] = d[3];
                }
            } else {
                if (r0 < N_NODES) {
                    if (c0     < N_NODES) out[(long)r0 * N_NODES + c0]     = d[0];
                    if (c0 + 1 < N_NODES) out[(long)r0 * N_NODES + c0 + 1] = d[1];
                }
                if (r0 + 8 < N_NODES) {
                    if (c0     < N_NODES) out[(long)(r0 + 8) * N_NODES + c0]     = d[2];
                    if (c0 + 1 < N_NODES) out[(long)(r0 + 8) * N_NODES + c0 + 1] = d[3];
                }
                if (bi != bj) {
                    if (c0 < N_NODES) {
                        if (r0     < N_NODES) out[(long)c0 * N_NODES + r0]     = d[0];
                        if (r0 + 8 < N_NODES) out[(long)c0 * N_NODES + r0 + 8] = d[2];
                    }
                    if (c0 + 1 < N_NODES) {
                        if (r0     < N_NODES) out[(long)(c0 + 1) * N_NODES + r0]     = d[1];
                        if (r0 + 8 < N_NODES) out[(long)(c0 + 1) * N_NODES + r0 + 8] = d[3];
                    }
                }
            }
        }
    }
}

extern "C" void kernel_launch(void* const* d_in, const int* in_sizes, int n_in,
                              void* d_out, int out_size) {
    // Identify inputs by element count (order-proof).
    const float* x  = nullptr;
    const void*  ei = nullptr;
    const float* W  = nullptr;
    const float* b  = nullptr;
    for (int i = 0; i < n_in; i++) {
        switch (in_sizes[i]) {
            case N_NODES * NHID: x  = (const float*)d_in[i]; break;
            case 2 * NEDGE:      ei = d_in[i];               break;
            case NHID * NHID:    W  = (const float*)d_in[i]; break;
            case NHID:           b  = (const float*)d_in[i]; break;
            default: break;
        }
    }
    float* out = (float*)d_out;

    k_zero   <<<512, 256>>>();
    k_detect <<<(NEDGE + 255) / 256, 256>>>((const int*)ei);
    k_convert<<<(NEDGE + 255) / 256, 256>>>(ei);
    k_hist   <<<(NEDGE + 255) / 256, 256>>>();
    k_scan   <<<1, 256>>>();
    k_dinv   <<<(N_NODES + 255) / 256, 256>>>();
    k_fill   <<<(NEDGE + 255) / 256, 256>>>();
    k_xw     <<<N_NODES, NHID>>>(x, W);
    k_spmm   <<<N_NODES, NHID>>>(b);
    dim3 gg(NT, NT);
    k_gemm<<<gg, 256>>>(out);
}

// round 6
// speedup vs baseline: 4.0675x; 2.0663x over previous
#include <cuda_runtime.h>
#include <cuda_bf16.h>

#define N_NODES 10000
#define NHID    128
#define NEDGE   320000
#define NT      79            // ceil(10000/128)
#define NPAD    (NT * 128)    // 10112
#define GEMM_SMEM 67584       // max(A+B tiles 64KB, Dsh 128*132*4)

__device__ __forceinline__ unsigned smem_u32(const void* p) {
    unsigned a;
    asm("{ .reg .u64 t; cvta.to.shared.u64 t, %1; cvt.u32.u64 %0, t; }"
        : "=r"(a) : "l"(p));
    return a;
}

// ---------------- scratch ----------------
__device__ float          g_xw  [N_NODES * NHID];
__device__ __nv_bfloat16  g_hb  [NPAD   * NHID];
__device__ float          g_dinv[N_NODES];
__device__ int            g_row [NEDGE];
__device__ int            g_col [NEDGE];
__device__ int            g_cnt [N_NODES];
__device__ int            g_base[N_NODES];
__device__ int            g_cur [N_NODES];
__device__ int            g_src [NEDGE];

// ---- convert (edge_index is int32) + zero counters + zero g_hb pad rows ----
__global__ void k_convert(const int* __restrict__ p) {
    int e = blockIdx.x * blockDim.x + threadIdx.x;
    int total = gridDim.x * blockDim.x;
    for (int t = e; t < N_NODES; t += total) { g_cnt[t] = 0; g_cur[t] = 0; }
    for (int t = e; t < (NPAD - N_NODES) * NHID; t += total)
        g_hb[N_NODES * NHID + t] = __float2bfloat16(0.0f);
    if (e < NEDGE) {
        int r = p[e], c = p[NEDGE + e];
        if ((unsigned)r >= N_NODES) r = 0;
        if ((unsigned)c >= N_NODES) c = 0;
        g_row[e] = r; g_col[e] = c;
    }
}

__global__ void k_hist() {
    int e = blockIdx.x * blockDim.x + threadIdx.x;
    if (e < NEDGE) atomicAdd(&g_cnt[g_col[e]], 1);
}

// ---- exclusive prefix sum (single block) ----
__global__ void k_scan() {
    __shared__ int sums[256];
    const int CH = 40;
    int t = threadIdx.x;
    int s = 0;
    for (int j = 0; j < CH; j++) {
        int n = t * CH + j;
        if (n < N_NODES) s += g_cnt[n];
    }
    sums[t] = s;
    __syncthreads();
    for (int off = 1; off < 256; off <<= 1) {
        int v = (t >= off) ? sums[t - off] : 0;
        __syncthreads();
        sums[t] += v;
        __syncthreads();
    }
    int run = (t > 0) ? sums[t - 1] : 0;
    for (int j = 0; j < CH; j++) {
        int n = t * CH + j;
        if (n < N_NODES) { g_base[n] = run; run += g_cnt[n]; }
    }
}

// ---- CSR fill + dinv fused ----
__global__ void k_fill() {
    int e = blockIdx.x * blockDim.x + threadIdx.x;
    if (e < N_NODES) g_dinv[e] = rsqrtf((float)g_cnt[e] + 1.0f);
    if (e < NEDGE) {
        int c = g_col[e];
        int pos = g_base[c] + atomicAdd(&g_cur[c], 1);
        g_src[pos] = g_row[e];
    }
}

// ---- xw = x @ W ----
__global__ void k_xw(const float* __restrict__ x, const float* __restrict__ W) {
    __shared__ float xs[NHID];
    int n = blockIdx.x;
    int t = threadIdx.x;
    xs[t] = x[n * NHID + t];
    __syncthreads();
    float acc = 0.0f;
#pragma unroll 8
    for (int k = 0; k < NHID; k++)
        acc = fmaf(xs[k], W[k * NHID + t], acc);
    g_xw[n * NHID + t] = acc;
}

// ---- SpMM gather + self-loop + bias + relu + bf16, fused ----
__global__ void k_spmm(const float* __restrict__ b) {
    int c = blockIdx.x;
    int t = threadIdx.x;
    int base = g_base[c];
    int cnt  = g_cnt[c];
    float acc = 0.0f;
    int r = (cnt > 0) ? g_src[base] : 0;
    for (int i = 0; i < cnt; i++) {
        int rn = (i + 1 < cnt) ? g_src[base + i + 1] : 0;
        acc = fmaf(g_dinv[r], g_xw[r * NHID + t], acc);
        r = rn;
    }
    float dc = g_dinv[c];
    float v  = dc * acc + dc * dc * g_xw[c * NHID + t] + b[t];
    g_hb[c * NHID + t] = __float2bfloat16(fmaxf(v, 0.0f));
}

// ---- out = h @ h^T : bf16 mma.sync + ldmatrix, upper-tri + smem-transpose mirror ----
// smem tile layout: 128 rows x 256B, byte = row*256 + ((kc ^ (row&7))*16), kc=0..15
__global__ void __launch_bounds__(256) k_gemm(float* __restrict__ out) {
    extern __shared__ char smem[];
    int bi = blockIdx.y, bj = blockIdx.x;
    if (bj < bi) return;
    bool diag = (bi == bj);

    unsigned sbase = smem_u32(smem);
    unsigned sA = sbase, sB = sbase + 32768u;

    int t = threadIdx.x, lane = t & 31, wid = t >> 5;
    const __nv_bfloat16* gA = g_hb + (size_t)bi * 128 * NHID;
    const __nv_bfloat16* gB = g_hb + (size_t)bj * 128 * NHID;

    // load tiles (8 passes x 256 threads x 16B)
#pragma unroll
    for (int p = 0; p < 8; p++) {
        int chunk = p * 256 + t;            // 0..2047
        int row = chunk >> 4, kc = chunk & 15;
        unsigned off = (unsigned)row * 256u + (unsigned)((kc ^ (row & 7)) << 4);
        *(uint4*)(smem + off) = *(const uint4*)(gA + row * NHID + kc * 8);
        if (!diag)
            *(uint4*)(smem + 32768 + off) = *(const uint4*)(gB + row * NHID + kc * 8);
    }
    __syncthreads();

    unsigned bB = diag ? sA : sB;
    int wm = wid & 3;        // m: wm*32
    int wn = wid >> 2;       // n: wn*64
    int mat = lane >> 3, rin = lane & 7;
    int rowoff = rin + (mat & 1) * 8;
    int khalf  = mat >> 1;

    float acc[2][8][4] = {};

#pragma unroll
    for (int ks = 0; ks < 8; ks++) {
        int kc = ks * 2 + khalf;
        unsigned a[2][4];
#pragma unroll
        for (int mi = 0; mi < 2; mi++) {
            int row = wm * 32 + mi * 16 + rowoff;
            unsigned addr = sA + (unsigned)row * 256u + (unsigned)((kc ^ (row & 7)) << 4);
            asm volatile("ldmatrix.sync.aligned.m8n8.x4.shared.b16 {%0,%1,%2,%3}, [%4];"
                : "=r"(a[mi][0]), "=r"(a[mi][1]), "=r"(a[mi][2]), "=r"(a[mi][3])
                : "r"(addr));
        }
        unsigned bf[4][4];
#pragma unroll
        for (int nb = 0; nb < 4; nb++) {
            int row = wn * 64 + nb * 16 + rowoff;
            unsigned addr = bB + (unsigned)row * 256u + (unsigned)((kc ^ (row & 7)) << 4);
            asm volatile("ldmatrix.sync.aligned.m8n8.x4.shared.b16 {%0,%1,%2,%3}, [%4];"
                : "=r"(bf[nb][0]), "=r"(bf[nb][1]), "=r"(bf[nb][2]), "=r"(bf[nb][3])
                : "r"(addr));
        }
#pragma unroll
        for (int mi = 0; mi < 2; mi++)
#pragma unroll
            for (int nb = 0; nb < 4; nb++) {
                float* d0 = acc[mi][nb * 2 + 0];
                float* d1 = acc[mi][nb * 2 + 1];
                asm volatile(
                    "mma.sync.aligned.m16n8k16.row.col.f32.bf16.bf16.f32 "
                    "{%0,%1,%2,%3}, {%4,%5,%6,%7}, {%8,%9}, {%0,%1,%2,%3};"
                    : "+f"(d0[0]), "+f"(d0[1]), "+f"(d0[2]), "+f"(d0[3])
                    : "r"(a[mi][0]), "r"(a[mi][1]), "r"(a[mi][2]), "r"(a[mi][3]),
                      "r"(bf[nb][0]), "r"(bf[nb][2]));
                asm volatile(
                    "mma.sync.aligned.m16n8k16.row.col.f32.bf16.bf16.f32 "
                    "{%0,%1,%2,%3}, {%4,%5,%6,%7}, {%8,%9}, {%0,%1,%2,%3};"
                    : "+f"(d1[0]), "+f"(d1[1]), "+f"(d1[2]), "+f"(d1[3])
                    : "r"(a[mi][0]), "r"(a[mi][1]), "r"(a[mi][2]), "r"(a[mi][3]),
                      "r"(bf[nb][1]), "r"(bf[nb][3]));
            }
    }

    // stage result in smem (overwrites tiles; all fragment reads are done)
    __syncthreads();
    float* Dsh = (float*)smem;   // [128][132]
    int g = lane >> 2, tq = lane & 3;
#pragma unroll
    for (int mi = 0; mi < 2; mi++)
#pragma unroll
        for (int ni = 0; ni < 8; ni++) {
            int r = wm * 32 + mi * 16 + g;
            int c = wn * 64 + ni * 8 + 2 * tq;
            float* d = acc[mi][ni];
            Dsh[r * 132 + c]           = d[0];
            Dsh[r * 132 + c + 1]       = d[1];
            Dsh[(r + 8) * 132 + c]     = d[2];
            Dsh[(r + 8) * 132 + c + 1] = d[3];
        }
    __syncthreads();

    int r0 = bi * 128, c0 = bj * 128;
    int colw = lane * 4;
    int rblk = (t >> 5) * 16;
    bool interior = (bi < NT - 1) && (bj < NT - 1);

    if (interior) {
#pragma unroll 4
        for (int i = 0; i < 16; i++) {
            int row = rblk + i;
            float4 v = *(float4*)&Dsh[row * 132 + colw];
            *(float4*)&out[(size_t)(r0 + row) * N_NODES + c0 + colw] = v;
        }
        if (!diag) {
#pragma unroll 4
            for (int i = 0; i < 16; i++) {
                int col = rblk + i;
                float4 v = make_float4(Dsh[(colw + 0) * 132 + col],
                                       Dsh[(colw + 1) * 132 + col],
                                       Dsh[(colw + 2) * 132 + col],
                                       Dsh[(colw + 3) * 132 + col]);
                *(float4*)&out[(size_t)(c0 + col) * N_NODES + r0 + colw] = v;
            }
        }
    } else {
        for (int i = 0; i < 16; i++) {
            int row = rblk + i, gr = r0 + row;
            if (gr < N_NODES)
                for (int j = 0; j < 4; j++) {
                    int gc = c0 + colw + j;
                    if (gc < N_NODES)
                        out[(size_t)gr * N_NODES + gc] = Dsh[row * 132 + colw + j];
                }
        }
        if (!diag) {
            for (int i = 0; i < 16; i++) {
                int col = rblk + i, gr = c0 + col;
                if (gr < N_NODES)
                    for (int j = 0; j < 4; j++) {
                        int gc = r0 + colw + j;
                        if (gc < N_NODES)
                            out[(size_t)gr * N_NODES + gc] = Dsh[(colw + j) * 132 + col];
                    }
            }
        }
    }
}

extern "C" void kernel_launch(void* const* d_in, const int* in_sizes, int n_in,
                              void* d_out, int out_size) {
    const float* x  = nullptr;
    const int*   ei = nullptr;
    const float* W  = nullptr;
    const float* b  = nullptr;
    for (int i = 0; i < n_in; i++) {
        switch (in_sizes[i]) {
            case N_NODES * NHID: x  = (const float*)d_in[i]; break;
            case 2 * NEDGE:      ei = (const int*)d_in[i];   break;
            case NHID * NHID:    W  = (const float*)d_in[i]; break;
            case NHID:           b  = (const float*)d_in[i]; break;
            default: break;
        }
    }
    float* out = (float*)d_out;

    static int smem_set = 0;
    if (!smem_set) {
        cudaFuncSetAttribute(k_gemm, cudaFuncAttributeMaxDynamicSharedMemorySize,
                             GEMM_SMEM);
        smem_set = 1;
    }

    k_convert<<<(NEDGE + 255) / 256, 256>>>(ei);
    k_hist   <<<(NEDGE + 255) / 256, 256>>>();
    k_scan   <<<1, 256>>>();
    k_fill   <<<(NEDGE + 255) / 256, 256>>>();
    k_xw     <<<N_NODES, NHID>>>(x, W);
    k_spmm   <<<N_NODES, NHID>>>(b);
    dim3 gg(NT, NT);
    k_gemm<<<gg, 256, GEMM_SMEM>>>(out);
}

// round 7
// speedup vs baseline: 4.2263x; 1.0390x over previous
#include <cuda_runtime.h>
#include <cuda_bf16.h>

#define N_NODES 10000
#define NHID    128
#define NEDGE   320000
#define NT      79            // ceil(10000/128)
#define NPAD    (NT * 128)    // 10112
#define DS      129           // Dsh row stride (129 mod 32 = 1 -> conflict-free cols)
#define GEMM_SMEM 66048       // max(A+B tiles 65536, 128*129*4 = 66048)

__device__ __forceinline__ unsigned smem_u32(const void* p) {
    unsigned a;
    asm("{ .reg .u64 t; cvta.to.shared.u64 t, %1; cvt.u32.u64 %0, t; }"
        : "=r"(a) : "l"(p));
    return a;
}

// ---------------- scratch ----------------
__device__ float          g_xw  [N_NODES * NHID];
__device__ __nv_bfloat16  g_hb  [NPAD   * NHID];
__device__ float          g_dinv[N_NODES];
__device__ int            g_cnt [N_NODES];
__device__ int            g_base[N_NODES];
__device__ int            g_cur [N_NODES];
__device__ int            g_src [NEDGE];

// ---- zero counters + g_hb pad rows (graph replay: re-run every launch) ----
__global__ void k_zero() {
    int i = blockIdx.x * blockDim.x + threadIdx.x;
    int total = gridDim.x * blockDim.x;
    for (int t = i; t < N_NODES; t += total) { g_cnt[t] = 0; g_cur[t] = 0; }
    for (int t = i; t < (NPAD - N_NODES) * NHID; t += total)
        g_hb[N_NODES * NHID + t] = __float2bfloat16(0.0f);
}

// ---- histogram of incoming edges at target (reads int32 edge buffer directly) ----
__global__ void k_hist(const int* __restrict__ p) {
    int e = blockIdx.x * blockDim.x + threadIdx.x;
    if (e < NEDGE) {
        int c = p[NEDGE + e];
        if ((unsigned)c >= N_NODES) c = 0;
        atomicAdd(&g_cnt[c], 1);
    }
}

// ---- exclusive prefix sum (single block) ----
__global__ void k_scan() {
    __shared__ int sums[256];
    const int CH = 40;
    int t = threadIdx.x;
    int s = 0;
    for (int j = 0; j < CH; j++) {
        int n = t * CH + j;
        if (n < N_NODES) s += g_cnt[n];
    }
    sums[t] = s;
    __syncthreads();
    for (int off = 1; off < 256; off <<= 1) {
        int v = (t >= off) ? sums[t - off] : 0;
        __syncthreads();
        sums[t] += v;
        __syncthreads();
    }
    int run = (t > 0) ? sums[t - 1] : 0;
    for (int j = 0; j < CH; j++) {
        int n = t * CH + j;
        if (n < N_NODES) { g_base[n] = run; run += g_cnt[n]; }
    }
}

// ---- CSR fill + dinv fused (reads edge buffer directly) ----
__global__ void k_fill(const int* __restrict__ p) {
    int e = blockIdx.x * blockDim.x + threadIdx.x;
    if (e < N_NODES) g_dinv[e] = rsqrtf((float)g_cnt[e] + 1.0f);
    if (e < NEDGE) {
        int r = p[e], c = p[NEDGE + e];
        if ((unsigned)r >= N_NODES) r = 0;
        if ((unsigned)c >= N_NODES) c = 0;
        int pos = g_base[c] + atomicAdd(&g_cur[c], 1);
        g_src[pos] = r;
    }
}

// ---- xw = x @ W ----
__global__ void k_xw(const float* __restrict__ x, const float* __restrict__ W) {
    __shared__ float xs[NHID];
    int n = blockIdx.x;
    int t = threadIdx.x;
    xs[t] = x[n * NHID + t];
    __syncthreads();
    float acc = 0.0f;
#pragma unroll 8
    for (int k = 0; k < NHID; k++)
        acc = fmaf(xs[k], W[k * NHID + t], acc);
    g_xw[n * NHID + t] = acc;
}

// ---- SpMM gather + self-loop + bias + relu + bf16, fused ----
__global__ void k_spmm(const float* __restrict__ b) {
    int c = blockIdx.x;
    int t = threadIdx.x;
    int base = g_base[c];
    int cnt  = g_cnt[c];
    float acc = 0.0f;
    int r = (cnt > 0) ? g_src[base] : 0;
    for (int i = 0; i < cnt; i++) {
        int rn = (i + 1 < cnt) ? g_src[base + i + 1] : 0;
        acc = fmaf(g_dinv[r], g_xw[r * NHID + t], acc);
        r = rn;
    }
    float dc = g_dinv[c];
    float v  = dc * acc + dc * dc * g_xw[c * NHID + t] + b[t];
    g_hb[c * NHID + t] = __float2bfloat16(fmaxf(v, 0.0f));
}

// ---- out = h @ h^T : bf16 mma.sync + ldmatrix, upper-tri + conflict-free mirror ----
__global__ void __launch_bounds__(256) k_gemm(float* __restrict__ out) {
    extern __shared__ char smem[];
    int bi = blockIdx.y, bj = blockIdx.x;
    if (bj < bi) return;
    bool diag = (bi == bj);

    unsigned sA = smem_u32(smem);
    unsigned sB = sA + 32768u;

    int t = threadIdx.x, lane = t & 31, wid = t >> 5;
    const __nv_bfloat16* gA = g_hb + (size_t)bi * 128 * NHID;
    const __nv_bfloat16* gB = g_hb + (size_t)bj * 128 * NHID;

    // load tiles (8 passes x 256 threads x 16B); XOR-16B swizzle per row
#pragma unroll
    for (int p = 0; p < 8; p++) {
        int chunk = p * 256 + t;            // 0..2047
        int row = chunk >> 4, kc = chunk & 15;
        unsigned off = (unsigned)row * 256u + (unsigned)((kc ^ (row & 7)) << 4);
        *(uint4*)(smem + off) = *(const uint4*)(gA + row * NHID + kc * 8);
        if (!diag)
            *(uint4*)(smem + 32768 + off) = *(const uint4*)(gB + row * NHID + kc * 8);
    }
    __syncthreads();

    unsigned bB = diag ? sA : sB;
    int wm = wid & 3;        // m: wm*32
    int wn = wid >> 2;       // n: wn*64
    int mat = lane >> 3, rin = lane & 7;
    int rowoff = rin + (mat & 1) * 8;
    int khalf  = mat >> 1;

    float acc[2][8][4] = {};

#pragma unroll
    for (int ks = 0; ks < 8; ks++) {
        int kc = ks * 2 + khalf;
        unsigned a[2][4];
#pragma unroll
        for (int mi = 0; mi < 2; mi++) {
            int row = wm * 32 + mi * 16 + rowoff;
            unsigned addr = sA + (unsigned)row * 256u + (unsigned)((kc ^ (row & 7)) << 4);
            asm volatile("ldmatrix.sync.aligned.m8n8.x4.shared.b16 {%0,%1,%2,%3}, [%4];"
                : "=r"(a[mi][0]), "=r"(a[mi][1]), "=r"(a[mi][2]), "=r"(a[mi][3])
                : "r"(addr));
        }
        unsigned bf[4][4];
#pragma unroll
        for (int nb = 0; nb < 4; nb++) {
            int row = wn * 64 + nb * 16 + rowoff;
            unsigned addr = bB + (unsigned)row * 256u + (unsigned)((kc ^ (row & 7)) << 4);
            asm volatile("ldmatrix.sync.aligned.m8n8.x4.shared.b16 {%0,%1,%2,%3}, [%4];"
                : "=r"(bf[nb][0]), "=r"(bf[nb][1]), "=r"(bf[nb][2]), "=r"(bf[nb][3])
                : "r"(addr));
        }
#pragma unroll
        for (int mi = 0; mi < 2; mi++)
#pragma unroll
            for (int nb = 0; nb < 4; nb++) {
                float* d0 = acc[mi][nb * 2 + 0];
                float* d1 = acc[mi][nb * 2 + 1];
                asm volatile(
                    "mma.sync.aligned.m16n8k16.row.col.f32.bf16.bf16.f32 "
                    "{%0,%1,%2,%3}, {%4,%5,%6,%7}, {%8,%9}, {%0,%1,%2,%3};"
                    : "+f"(d0[0]), "+f"(d0[1]), "+f"(d0[2]), "+f"(d0[3])
                    : "r"(a[mi][0]), "r"(a[mi][1]), "r"(a[mi][2]), "r"(a[mi][3]),
                      "r"(bf[nb][0]), "r"(bf[nb][2]));
                asm volatile(
                    "mma.sync.aligned.m16n8k16.row.col.f32.bf16.bf16.f32 "
                    "{%0,%1,%2,%3}, {%4,%5,%6,%7}, {%8,%9}, {%0,%1,%2,%3};"
                    : "+f"(d1[0]), "+f"(d1[1]), "+f"(d1[2]), "+f"(d1[3])
                    : "r"(a[mi][0]), "r"(a[mi][1]), "r"(a[mi][2]), "r"(a[mi][3]),
                      "r"(bf[nb][1]), "r"(bf[nb][3]));
            }
    }

    // stage result in smem, row stride DS=129 (overwrites tiles)
    __syncthreads();
    float* Dsh = (float*)smem;
    int g = lane >> 2, tq = lane & 3;
#pragma unroll
    for (int mi = 0; mi < 2; mi++)
#pragma unroll
        for (int ni = 0; ni < 8; ni++) {
            int r = wm * 32 + mi * 16 + g;
            int c = wn * 64 + ni * 8 + 2 * tq;
            float* d = acc[mi][ni];
            Dsh[r * DS + c]           = d[0];
            Dsh[r * DS + c + 1]       = d[1];
            Dsh[(r + 8) * DS + c]     = d[2];
            Dsh[(r + 8) * DS + c + 1] = d[3];
        }
    __syncthreads();

    int r0 = bi * 128, c0 = bj * 128;
    bool interior = (bi < NT - 1) && (bj < NT - 1);

    if (interior) {
        // direct: warp handles 16 rows; lanes scan 128 cols scalar (conflict-free, coalesced)
#pragma unroll 2
        for (int i = 0; i < 16; i++) {
            int row = wid * 16 + i;
            float* orow = out + (size_t)(r0 + row) * N_NODES + c0;
            const float* srow = Dsh + row * DS;
#pragma unroll
            for (int s = 0; s < 4; s++)
                orow[lane + 32 * s] = srow[lane + 32 * s];
        }
        if (!diag) {
            // mirror: warp handles 16 tile-cols; lanes scan 128 rows scalar
            // bank of Dsh[(lane+32s)*129 + c] = (lane + c) mod 32 -> conflict-free
#pragma unroll 2
            for (int i = 0; i < 16; i++) {
                int c = wid * 16 + i;
                float* orow = out + (size_t)(c0 + c) * N_NODES + r0;
                const float* scol = Dsh + c;
#pragma unroll
                for (int s = 0; s < 4; s++)
                    orow[lane + 32 * s] = scol[(lane + 32 * s) * DS];
            }
        }
    } else {
        for (int i = 0; i < 16; i++) {
            int row = wid * 16 + i, gr = r0 + row;
            if (gr < N_NODES)
                for (int s = 0; s < 4; s++) {
                    int gc = c0 + lane + 32 * s;
                    if (gc < N_NODES)
                        out[(size_t)gr * N_NODES + gc] = Dsh[row * DS + lane + 32 * s];
                }
        }
        if (!diag) {
            for (int i = 0; i < 16; i++) {
                int c = wid * 16 + i, gr = c0 + c;
                if (gr < N_NODES)
                    for (int s = 0; s < 4; s++) {
                        int gc = r0 + lane + 32 * s;
                        if (gc < N_NODES)
                            out[(size_t)gr * N_NODES + gc] = Dsh[(lane + 32 * s) * DS + c];
                    }
            }
        }
    }
}

extern "C" void kernel_launch(void* const* d_in, const int* in_sizes, int n_in,
                              void* d_out, int out_size) {
    const float* x  = nullptr;
    const int*   ei = nullptr;
    const float* W  = nullptr;
    const float* b  = nullptr;
    for (int i = 0; i < n_in; i++) {
        switch (in_sizes[i]) {
            case N_NODES * NHID: x  = (const float*)d_in[i]; break;
            case 2 * NEDGE:      ei = (const int*)d_in[i];   break;
            case NHID * NHID:    W  = (const float*)d_in[i]; break;
            case NHID:           b  = (const float*)d_in[i]; break;
            default: break;
        }
    }
    float* out = (float*)d_out;

    static int smem_set = 0;
    if (!smem_set) {
        cudaFuncSetAttribute(k_gemm, cudaFuncAttributeMaxDynamicSharedMemorySize,
                             GEMM_SMEM);
        smem_set = 1;
    }

    k_zero <<<64, 256>>>();
    k_hist <<<(NEDGE + 255) / 256, 256>>>(ei);
    k_scan <<<1, 256>>>();
    k_fill <<<(NEDGE + 255) / 256, 256>>>(ei);
    k_xw   <<<N_NODES, NHID>>>(x, W);
    k_spmm <<<N_NODES, NHID>>>(b);
    dim3 gg(NT, NT);
    k_gemm<<<gg, 256, GEMM_SMEM>>>(out);
}